// round 1
// baseline (speedup 1.0000x reference)
#include <cuda_runtime.h>
#include <cuda_bf16.h>
#include <cstdint>

// Problem constants
#define H 64
#define B 16
#define L 512
#define OUT 2
#define TOKS_PER_BLOCK 8          // 1024 tokens per batch / 8 = 128 blocks per batch
#define BLOCKS_PER_BATCH (2 * L / TOKS_PER_BLOCK)   // 128
#define GRID1 (B * BLOCKS_PER_BATCH)                 // 2048

// Accumulator scratch: h[b][h] = sum over 1024 tokens of sos @ M_tok
__device__ float g_h[B * H];

// ---------------------------------------------------------------------------
// Kernel 0: zero the accumulator (graph-replay safe)
// ---------------------------------------------------------------------------
__global__ void zero_kernel() {
    g_h[threadIdx.x] = 0.0f;   // 1024 threads
}

// ---------------------------------------------------------------------------
// Kernel 1: token gather + sos contraction + per-batch accumulation
//
// Thread layout (256 threads):
//   h4 = tid & 15   -> handles output columns h = 4*h4 .. 4*h4+3 (one float4)
//   wg = tid >> 4   -> handles rows w = wg, wg+16, wg+32, wg+48
// Per token: 4 float4 loads per thread; a warp's 32 loads cover two full
// 256-byte matrix rows -> fully coalesced.
// ---------------------------------------------------------------------------
__global__ __launch_bounds__(256, 8)
void gather_contract_kernel(const int* __restrict__ s1,
                            const int* __restrict__ s2,
                            const float4* __restrict__ embed,
                            const float* __restrict__ sos)
{
    const int bl  = blockIdx.x;
    const int b   = bl / BLOCKS_PER_BATCH;
    const int j0  = (bl % BLOCKS_PER_BATCH) * TOKS_PER_BLOCK;  // token idx within [0,1024)
    const int tid = threadIdx.x;
    const int h4  = tid & 15;
    const int wg  = tid >> 4;

    const float sw0 = __ldg(&sos[wg]);
    const float sw1 = __ldg(&sos[wg + 16]);
    const float sw2 = __ldg(&sos[wg + 32]);
    const float sw3 = __ldg(&sos[wg + 48]);

    float4 acc = make_float4(0.f, 0.f, 0.f, 0.f);

    #pragma unroll
    for (int k = 0; k < TOKS_PER_BLOCK; k++) {
        const int j = j0 + k;
        const int tok = (j < L) ? __ldg(&s1[b * L + j])
                                : __ldg(&s2[b * L + (j - L)]);
        const float4* M = embed + (size_t)tok * (H * H / 4);  // 1024 float4 per row

        float4 m0 = __ldg(&M[(wg      ) * 16 + h4]);
        float4 m1 = __ldg(&M[(wg + 16) * 16 + h4]);
        float4 m2 = __ldg(&M[(wg + 32) * 16 + h4]);
        float4 m3 = __ldg(&M[(wg + 48) * 16 + h4]);

        acc.x = fmaf(sw0, m0.x, acc.x); acc.y = fmaf(sw0, m0.y, acc.y);
        acc.z = fmaf(sw0, m0.z, acc.z); acc.w = fmaf(sw0, m0.w, acc.w);
        acc.x = fmaf(sw1, m1.x, acc.x); acc.y = fmaf(sw1, m1.y, acc.y);
        acc.z = fmaf(sw1, m1.z, acc.z); acc.w = fmaf(sw1, m1.w, acc.w);
        acc.x = fmaf(sw2, m2.x, acc.x); acc.y = fmaf(sw2, m2.y, acc.y);
        acc.z = fmaf(sw2, m2.z, acc.z); acc.w = fmaf(sw2, m2.w, acc.w);
        acc.x = fmaf(sw3, m3.x, acc.x); acc.y = fmaf(sw3, m3.y, acc.y);
        acc.z = fmaf(sw3, m3.z, acc.z); acc.w = fmaf(sw3, m3.w, acc.w);
    }

    // Reduce the 16 wg-groups per output column via shared atomics, then one
    // global atomicAdd per column.
    __shared__ float sh[H];
    if (tid < H) sh[tid] = 0.f;
    __syncthreads();
    atomicAdd(&sh[h4 * 4 + 0], acc.x);
    atomicAdd(&sh[h4 * 4 + 1], acc.y);
    atomicAdd(&sh[h4 * 4 + 2], acc.z);
    atomicAdd(&sh[h4 * 4 + 3], acc.w);
    __syncthreads();
    if (tid < H) atomicAdd(&g_h[b * H + tid], sh[tid]);
}

// ---------------------------------------------------------------------------
// Kernel 2: tiny MLP classifier  out = relu(h @ w1^T + b1) @ w2^T + b2
// One block, 1024 threads: thread (b,j) computes hidden unit j of batch b.
// ---------------------------------------------------------------------------
__global__ void mlp_kernel(const float* __restrict__ w1,
                           const float* __restrict__ b1,
                           const float* __restrict__ w2,
                           const float* __restrict__ b2,
                           float* __restrict__ out)
{
    __shared__ float x[B][H];
    const int tid = threadIdx.x;           // 0..1023
    const int b = tid >> 6;
    const int j = tid & 63;

    float acc = __ldg(&b1[j]);
    #pragma unroll
    for (int k = 0; k < H; k++)
        acc = fmaf(g_h[b * H + k], __ldg(&w1[j * H + k]), acc);
    x[b][j] = fmaxf(acc, 0.f);
    __syncthreads();

    if (tid < B * OUT) {
        const int bb = tid >> 1;
        const int o  = tid & 1;
        float a = __ldg(&b2[o]);
        #pragma unroll
        for (int k = 0; k < H; k++)
            a = fmaf(x[bb][k], __ldg(&w2[o * H + k]), a);
        out[bb * OUT + o] = a;
    }
}

// ---------------------------------------------------------------------------
// Launch
// Inputs (metadata order): s1, s2, embed, sos, w1, b1, w2, b2
// ---------------------------------------------------------------------------
extern "C" void kernel_launch(void* const* d_in, const int* in_sizes, int n_in,
                              void* d_out, int out_size)
{
    const int*    s1    = (const int*)   d_in[0];
    const int*    s2    = (const int*)   d_in[1];
    const float4* embed = (const float4*)d_in[2];
    const float*  sos   = (const float*) d_in[3];
    const float*  w1    = (const float*) d_in[4];
    const float*  b1    = (const float*) d_in[5];
    const float*  w2    = (const float*) d_in[6];
    const float*  b2    = (const float*) d_in[7];
    float* out = (float*)d_out;

    zero_kernel<<<1, B * H>>>();
    gather_contract_kernel<<<GRID1, 256>>>(s1, s2, embed, sos);
    mlp_kernel<<<1, 1024>>>(w1, b1, w2, b2, out);
}

// round 2
// speedup vs baseline: 1.0298x; 1.0298x over previous
#include <cuda_runtime.h>
#include <cuda_bf16.h>
#include <cstdint>

// Problem constants
#define H 64
#define B 16
#define L 512
#define OUT 2
#define TOKS_PER_BLOCK 16
#define BLOCKS_PER_BATCH (2 * L / TOKS_PER_BLOCK)    // 64
#define GRID1 (B * BLOCKS_PER_BATCH)                 // 1024

// Accumulator scratch: h[b][h] = sum over 1024 tokens of sos @ M_tok.
// Zero-initialized at module load; mlp_kernel resets it to zero after reading,
// so every graph replay sees it zeroed. (No separate zero kernel needed.)
__device__ float g_h[B * H];

// ---------------------------------------------------------------------------
// Kernel 1: token gather + sos contraction + per-batch accumulation
//
// Thread layout (256 threads):
//   h4 = tid & 15   -> output columns h = 4*h4 .. 4*h4+3 (one float4)
//   wg = tid >> 4   -> rows w = wg, wg+16, wg+32, wg+48
// A warp's 32 LDG.128 cover two full 256-byte matrix rows -> fully coalesced.
// ---------------------------------------------------------------------------
__global__ __launch_bounds__(256, 8)
void gather_contract_kernel(const int* __restrict__ s1,
                            const int* __restrict__ s2,
                            const float4* __restrict__ embed,
                            const float* __restrict__ sos)
{
    const int bl  = blockIdx.x;
    const int b   = bl / BLOCKS_PER_BATCH;
    const int j0  = (bl % BLOCKS_PER_BATCH) * TOKS_PER_BLOCK;  // within [0, 1024)
    const int tid = threadIdx.x;
    const int h4  = tid & 15;
    const int wg  = tid >> 4;

    // This block's 16 tokens are entirely in s1 or entirely in s2.
    const int* sp = (j0 < L) ? (s1 + b * L + j0) : (s2 + b * L + (j0 - L));

    // Prefetch all token indices up front (uniform loads, broadcast from L1).
    int toks[TOKS_PER_BLOCK];
    #pragma unroll
    for (int k = 0; k < TOKS_PER_BLOCK; k++)
        toks[k] = __ldg(&sp[k]);

    const float sw0 = __ldg(&sos[wg]);
    const float sw1 = __ldg(&sos[wg + 16]);
    const float sw2 = __ldg(&sos[wg + 32]);
    const float sw3 = __ldg(&sos[wg + 48]);

    float4 acc = make_float4(0.f, 0.f, 0.f, 0.f);

    #pragma unroll 4
    for (int k = 0; k < TOKS_PER_BLOCK; k++) {
        const float4* M = embed + (size_t)toks[k] * (H * H / 4);

        float4 m0 = __ldg(&M[(wg      ) * 16 + h4]);
        float4 m1 = __ldg(&M[(wg + 16) * 16 + h4]);
        float4 m2 = __ldg(&M[(wg + 32) * 16 + h4]);
        float4 m3 = __ldg(&M[(wg + 48) * 16 + h4]);

        acc.x = fmaf(sw0, m0.x, acc.x); acc.y = fmaf(sw0, m0.y, acc.y);
        acc.z = fmaf(sw0, m0.z, acc.z); acc.w = fmaf(sw0, m0.w, acc.w);
        acc.x = fmaf(sw1, m1.x, acc.x); acc.y = fmaf(sw1, m1.y, acc.y);
        acc.z = fmaf(sw1, m1.z, acc.z); acc.w = fmaf(sw1, m1.w, acc.w);
        acc.x = fmaf(sw2, m2.x, acc.x); acc.y = fmaf(sw2, m2.y, acc.y);
        acc.z = fmaf(sw2, m2.z, acc.z); acc.w = fmaf(sw2, m2.w, acc.w);
        acc.x = fmaf(sw3, m3.x, acc.x); acc.y = fmaf(sw3, m3.y, acc.y);
        acc.z = fmaf(sw3, m3.z, acc.z); acc.w = fmaf(sw3, m3.w, acc.w);
    }

    // Warp reduce: lane l and l+16 hold the same columns for adjacent wg rows.
    acc.x += __shfl_down_sync(0xffffffffu, acc.x, 16);
    acc.y += __shfl_down_sync(0xffffffffu, acc.y, 16);
    acc.z += __shfl_down_sync(0xffffffffu, acc.z, 16);
    acc.w += __shfl_down_sync(0xffffffffu, acc.w, 16);

    __shared__ float sh[8][H];
    const int warp = tid >> 5;
    const int lane = tid & 31;
    if (lane < 16) {
        sh[warp][lane * 4 + 0] = acc.x;
        sh[warp][lane * 4 + 1] = acc.y;
        sh[warp][lane * 4 + 2] = acc.z;
        sh[warp][lane * 4 + 3] = acc.w;
    }
    __syncthreads();
    if (tid < H) {
        float s = 0.f;
        #pragma unroll
        for (int w = 0; w < 8; w++) s += sh[w][tid];
        atomicAdd(&g_h[b * H + tid], s);
    }
}

// ---------------------------------------------------------------------------
// Kernel 2: tiny MLP classifier  out = relu(h @ w1^T + b1) @ w2^T + b2
// One block, 1024 threads: thread (b,j) computes hidden unit j of batch b.
// Also resets g_h to zero afterwards (replay invariant).
// ---------------------------------------------------------------------------
__global__ void mlp_kernel(const float* __restrict__ w1,
                           const float* __restrict__ b1,
                           const float* __restrict__ w2,
                           const float* __restrict__ b2,
                           float* __restrict__ out)
{
    __shared__ float x[B][H];
    const int tid = threadIdx.x;           // 0..1023
    const int b = tid >> 6;
    const int j = tid & 63;

    float acc = __ldg(&b1[j]);
    #pragma unroll
    for (int k = 0; k < H; k++)
        acc = fmaf(g_h[b * H + k], __ldg(&w1[j * H + k]), acc);
    x[b][j] = fmaxf(acc, 0.f);
    __syncthreads();

    // Reset accumulator for the next graph replay (all reads done above).
    g_h[tid] = 0.0f;

    if (tid < B * OUT) {
        const int bb = tid >> 1;
        const int o  = tid & 1;
        float a = __ldg(&b2[o]);
        #pragma unroll
        for (int k = 0; k < H; k++)
            a = fmaf(x[bb][k], __ldg(&w2[o * H + k]), a);
        out[bb * OUT + o] = a;
    }
}

// ---------------------------------------------------------------------------
// Launch
// Inputs (metadata order): s1, s2, embed, sos, w1, b1, w2, b2
// ---------------------------------------------------------------------------
extern "C" void kernel_launch(void* const* d_in, const int* in_sizes, int n_in,
                              void* d_out, int out_size)
{
    const int*    s1    = (const int*)   d_in[0];
    const int*    s2    = (const int*)   d_in[1];
    const float4* embed = (const float4*)d_in[2];
    const float*  sos   = (const float*) d_in[3];
    const float*  w1    = (const float*) d_in[4];
    const float*  b1    = (const float*) d_in[5];
    const float*  w2    = (const float*) d_in[6];
    const float*  b2    = (const float*) d_in[7];
    float* out = (float*)d_out;

    gather_contract_kernel<<<GRID1, 256>>>(s1, s2, embed, sos);
    mlp_kernel<<<1, 1024>>>(w1, b1, w2, b2, out);
}

// round 3
// speedup vs baseline: 1.7144x; 1.6648x over previous
#include <cuda_runtime.h>
#include <cuda_bf16.h>
#include <cstdint>

// Problem constants
#define H 64
#define B 16
#define L 512
#define OUT 2
#define TOKS_PER_BLOCK 16
#define BLOCKS_PER_BATCH (2 * L / TOKS_PER_BLOCK)    // 64
#define GRID1 (B * BLOCKS_PER_BATCH)                 // 1024

// Accumulator scratch: h[b][h] = sum over 1024 tokens of sos @ M_tok.
// Zero-initialized at module load; mlp_kernel resets it to zero after reading,
// so every graph replay sees it zeroed.
__device__ float g_h[B * H];

// ---------------------------------------------------------------------------
// Kernel 1: token gather + sos contraction + per-batch accumulation
// (unchanged from R2 — it is near the memory roofline)
// ---------------------------------------------------------------------------
__global__ __launch_bounds__(256, 8)
void gather_contract_kernel(const int* __restrict__ s1,
                            const int* __restrict__ s2,
                            const float4* __restrict__ embed,
                            const float* __restrict__ sos)
{
    const int bl  = blockIdx.x;
    const int b   = bl / BLOCKS_PER_BATCH;
    const int j0  = (bl % BLOCKS_PER_BATCH) * TOKS_PER_BLOCK;  // within [0, 1024)
    const int tid = threadIdx.x;
    const int h4  = tid & 15;
    const int wg  = tid >> 4;

    // This block's 16 tokens are entirely in s1 or entirely in s2.
    const int* sp = (j0 < L) ? (s1 + b * L + j0) : (s2 + b * L + (j0 - L));

    int toks[TOKS_PER_BLOCK];
    #pragma unroll
    for (int k = 0; k < TOKS_PER_BLOCK; k++)
        toks[k] = __ldg(&sp[k]);

    const float sw0 = __ldg(&sos[wg]);
    const float sw1 = __ldg(&sos[wg + 16]);
    const float sw2 = __ldg(&sos[wg + 32]);
    const float sw3 = __ldg(&sos[wg + 48]);

    float4 acc = make_float4(0.f, 0.f, 0.f, 0.f);

    #pragma unroll 4
    for (int k = 0; k < TOKS_PER_BLOCK; k++) {
        const float4* M = embed + (size_t)toks[k] * (H * H / 4);

        float4 m0 = __ldg(&M[(wg      ) * 16 + h4]);
        float4 m1 = __ldg(&M[(wg + 16) * 16 + h4]);
        float4 m2 = __ldg(&M[(wg + 32) * 16 + h4]);
        float4 m3 = __ldg(&M[(wg + 48) * 16 + h4]);

        acc.x = fmaf(sw0, m0.x, acc.x); acc.y = fmaf(sw0, m0.y, acc.y);
        acc.z = fmaf(sw0, m0.z, acc.z); acc.w = fmaf(sw0, m0.w, acc.w);
        acc.x = fmaf(sw1, m1.x, acc.x); acc.y = fmaf(sw1, m1.y, acc.y);
        acc.z = fmaf(sw1, m1.z, acc.z); acc.w = fmaf(sw1, m1.w, acc.w);
        acc.x = fmaf(sw2, m2.x, acc.x); acc.y = fmaf(sw2, m2.y, acc.y);
        acc.z = fmaf(sw2, m2.z, acc.z); acc.w = fmaf(sw2, m2.w, acc.w);
        acc.x = fmaf(sw3, m3.x, acc.x); acc.y = fmaf(sw3, m3.y, acc.y);
        acc.w = fmaf(sw3, m3.w, acc.w); acc.z = fmaf(sw3, m3.z, acc.z);
    }

    // Warp reduce: lane l and l+16 hold the same columns for adjacent wg rows.
    acc.x += __shfl_down_sync(0xffffffffu, acc.x, 16);
    acc.y += __shfl_down_sync(0xffffffffu, acc.y, 16);
    acc.z += __shfl_down_sync(0xffffffffu, acc.z, 16);
    acc.w += __shfl_down_sync(0xffffffffu, acc.w, 16);

    __shared__ float sh[8][H];
    const int warp = tid >> 5;
    const int lane = tid & 31;
    if (lane < 16) {
        sh[warp][lane * 4 + 0] = acc.x;
        sh[warp][lane * 4 + 1] = acc.y;
        sh[warp][lane * 4 + 2] = acc.z;
        sh[warp][lane * 4 + 3] = acc.w;
    }
    __syncthreads();
    if (tid < H) {
        float s = 0.f;
        #pragma unroll
        for (int w = 0; w < 8; w++) s += sh[w][tid];
        atomicAdd(&g_h[b * H + tid], s);
    }
}

// ---------------------------------------------------------------------------
// Kernel 2: tiny MLP classifier  out = relu(h @ w1^T + b1) @ w2^T + b2
//
// R3 fix: the naive per-thread w1[j*64+k] loads were 32-way uncoalesced
// (32 wavefronts per LDG, 65536 wavefronts on one SM -> 38us). Now w1 is
// staged into padded SMEM with ONE coalesced pass; the compute phase reads
// w1s[j][k] at bank (j+k)%32 -> conflict-free LDS, ~2us total.
// ---------------------------------------------------------------------------
__global__ __launch_bounds__(1024, 1)
void mlp_kernel(const float* __restrict__ w1,
                const float* __restrict__ b1,
                const float* __restrict__ w2,
                const float* __restrict__ b2,
                float* __restrict__ out)
{
    __shared__ float w1s[H][H + 1];   // padded: bank(j*65+k) = (j+k)%32
    __shared__ float hs[B * H];
    __shared__ float x[B][H];

    const int tid = threadIdx.x;      // 0..1023

    // Coalesced stage of w1 (64x64 floats = 4096) and g_h (1024).
    #pragma unroll
    for (int idx = tid; idx < H * H; idx += 1024)
        w1s[idx >> 6][idx & 63] = __ldg(&w1[idx]);
    hs[tid] = g_h[tid];
    g_h[tid] = 0.0f;                  // reset for next graph replay
    __syncthreads();

    const int b = tid >> 6;
    const int j = tid & 63;

    float acc = __ldg(&b1[j]);
    #pragma unroll
    for (int k = 0; k < H; k++)
        acc = fmaf(hs[b * H + k], w1s[j][k], acc);
    x[b][j] = fmaxf(acc, 0.f);
    __syncthreads();

    if (tid < B * OUT) {
        const int bb = tid >> 1;
        const int o  = tid & 1;
        float a = __ldg(&b2[o]);
        #pragma unroll
        for (int k = 0; k < H; k++)
            a = fmaf(x[bb][k], __ldg(&w2[o * H + k]), a);
        out[bb * OUT + o] = a;
    }
}

// ---------------------------------------------------------------------------
// Launch
// Inputs (metadata order): s1, s2, embed, sos, w1, b1, w2, b2
// ---------------------------------------------------------------------------
extern "C" void kernel_launch(void* const* d_in, const int* in_sizes, int n_in,
                              void* d_out, int out_size)
{
    const int*    s1    = (const int*)   d_in[0];
    const int*    s2    = (const int*)   d_in[1];
    const float4* embed = (const float4*)d_in[2];
    const float*  sos   = (const float*) d_in[3];
    const float*  w1    = (const float*) d_in[4];
    const float*  b1    = (const float*) d_in[5];
    const float*  w2    = (const float*) d_in[6];
    const float*  b2    = (const float*) d_in[7];
    float* out = (float*)d_out;

    gather_contract_kernel<<<GRID1, 256>>>(s1, s2, embed, sos);
    mlp_kernel<<<1, 1024>>>(w1, b1, w2, b2, out);
}